// round 1
// baseline (speedup 1.0000x reference)
#include <cuda_runtime.h>
#include <cstdint>

// Problem constants (fixed by reference setup_inputs)
#define NXR 16384      // rows of X
#define NYC 16384      // rows of Y (= columns of sim)
#define CDIM 128       // feature dim
#define KSEL 15        // top-k
#define SIM_SCALE 5.0f // 1/TAU, TAU=0.2

// Scratch: Y transposed to [CDIM][NYC] so column loads are coalesced.
__device__ float g_Yt[CDIM * NYC];

// ---------------------------------------------------------------------------
// Kernel 1: transpose Y [NYC][CDIM] -> g_Yt [CDIM][NYC]
// ---------------------------------------------------------------------------
__global__ void transpose_y_kernel(const float* __restrict__ Y) {
    __shared__ float t[32][33];
    int cblk = blockIdx.x * 32;   // block of Y-rows (sim columns)
    int kblk = blockIdx.y * 32;   // block of feature dims
    int tx = threadIdx.x;         // 0..31
    int ty = threadIdx.y;         // 0..7

    #pragma unroll
    for (int i = ty; i < 32; i += 8)
        t[i][tx] = Y[(size_t)(cblk + i) * CDIM + (kblk + tx)];
    __syncthreads();
    #pragma unroll
    for (int i = ty; i < 32; i += 8)
        g_Yt[(size_t)(kblk + i) * NYC + (cblk + tx)] = t[tx][i];
}

// ---------------------------------------------------------------------------
// Kernel 2: fused sim-GEMM + per-row top-15 + softmax
// CTA: 256 threads = 8 warps, 4 rows per warp -> 32 rows per CTA.
// Each warp streams all 16384 columns in tiles of 128 (lane handles 4
// consecutive columns), maintaining a sorted top-15 list per row in smem.
// ---------------------------------------------------------------------------
__global__ __launch_bounds__(256, 3)
void simtopk_kernel(const float* __restrict__ X, float* __restrict__ out,
                    int out_size) {
    __shared__ float sX[32][128];     // X tile (raw, unscaled)
    __shared__ float sV[32][16];      // per-row top-15 values (raw dot)
    __shared__ int   sI[32][16];      // per-row top-15 column indices

    const int tid  = threadIdx.x;
    const int warp = tid >> 5;
    const int lane = tid & 31;
    const int rowBase = blockIdx.x * 32;
    const int r0 = warp * 4;          // first local row of this warp

    // Load X tile (32 rows x 128) via float4
    {
        const float4* X4 = (const float4*)(X + (size_t)rowBase * CDIM);
        float4* sX4 = (float4*)sX;
        #pragma unroll
        for (int i = tid; i < 32 * 32; i += 256) sX4[i] = X4[i];
    }
    // Init top-k lists
    for (int i = tid; i < 32 * 16; i += 256) {
        ((float*)sV)[i] = -__int_as_float(0x7f800000); // -inf
        ((int*)sI)[i]   = 0x7fffffff;
    }
    __syncthreads();

    const float4* sX4row0 = (const float4*)sX[r0 + 0];
    const float4* sX4row1 = (const float4*)sX[r0 + 1];
    const float4* sX4row2 = (const float4*)sX[r0 + 2];
    const float4* sX4row3 = (const float4*)sX[r0 + 3];

    for (int tile = 0; tile < NYC / 128; ++tile) {
        const int colbase = tile * 128;
        const int mycol   = colbase + lane * 4;  // 4 consecutive cols per lane

        float acc[4][4];
        #pragma unroll
        for (int r = 0; r < 4; ++r)
            #pragma unroll
            for (int j = 0; j < 4; ++j) acc[r][j] = 0.0f;

        // yb[k * (NYC/4)] = float4 of Yt[k][mycol..mycol+3]
        const float4* yb = ((const float4*)g_Yt) + (colbase >> 2) + lane;

        #pragma unroll 4
        for (int k4 = 0; k4 < CDIM / 4; ++k4) {
            float4 x0 = sX4row0[k4];
            float4 x1 = sX4row1[k4];
            float4 x2 = sX4row2[k4];
            float4 x3 = sX4row3[k4];
            #pragma unroll
            for (int kk = 0; kk < 4; ++kk) {
                float4 yv = yb[(size_t)(k4 * 4 + kk) * (NYC / 4)];
                float a0 = ((const float*)&x0)[kk];
                float a1 = ((const float*)&x1)[kk];
                float a2 = ((const float*)&x2)[kk];
                float a3 = ((const float*)&x3)[kk];
                acc[0][0] += a0 * yv.x; acc[0][1] += a0 * yv.y;
                acc[0][2] += a0 * yv.z; acc[0][3] += a0 * yv.w;
                acc[1][0] += a1 * yv.x; acc[1][1] += a1 * yv.y;
                acc[1][2] += a1 * yv.z; acc[1][3] += a1 * yv.w;
                acc[2][0] += a2 * yv.x; acc[2][1] += a2 * yv.y;
                acc[2][2] += a2 * yv.z; acc[2][3] += a2 * yv.w;
                acc[3][0] += a3 * yv.x; acc[3][1] += a3 * yv.y;
                acc[3][2] += a3 * yv.z; acc[3][3] += a3 * yv.w;
            }
        }

        // Top-k update (warp-cooperative, rows are warp-private)
        #pragma unroll
        for (int r = 0; r < 4; ++r) {
            const int rl = r0 + r;
            float thr = sV[rl][KSEL - 1];
            #pragma unroll
            for (int j = 0; j < 4; ++j) {
                float v = acc[r][j];
                int   c = mycol + j;
                unsigned m = __ballot_sync(0xffffffffu, v > thr);
                while (m) {
                    int src = __ffs(m) - 1;
                    m &= m - 1;
                    float cv = __shfl_sync(0xffffffffu, v, src);
                    int   cc = __shfl_sync(0xffffffffu, c, src);
                    if (lane == 0) {
                        float lv = sV[rl][KSEL - 1];
                        int   li = sI[rl][KSEL - 1];
                        if (cv > lv || (cv == lv && cc < li)) {
                            int p = KSEL - 1;
                            while (p > 0) {
                                float pv = sV[rl][p - 1];
                                int   pi = sI[rl][p - 1];
                                if (cv > pv || (cv == pv && cc < pi)) {
                                    sV[rl][p] = pv; sI[rl][p] = pi; --p;
                                } else break;
                            }
                            sV[rl][p] = cv; sI[rl][p] = cc;
                        }
                    }
                    __syncwarp(0xffffffffu);
                    thr = sV[rl][KSEL - 1];
                    m &= __ballot_sync(0xffffffffu, v > thr);
                }
            }
        }
        // Keep warps lock-stepped for L1 reuse of Yt tiles.
        __syncthreads();
    }

    // Finalize: softmax over scaled top-15, write outputs.
    const bool writeIdx = (out_size >= 2 * NXR * KSEL);
    #pragma unroll
    for (int r = 0; r < 4; ++r) {
        const int rl  = r0 + r;
        const int row = rowBase + rl;
        float v  = (lane < KSEL) ? sV[rl][lane] * SIM_SCALE : 0.0f;
        float mx = __shfl_sync(0xffffffffu, v, 0);     // list[0] is the max
        float e  = (lane < KSEL) ? expf(v - mx) : 0.0f;
        float s  = e;
        #pragma unroll
        for (int off = 16; off > 0; off >>= 1)
            s += __shfl_xor_sync(0xffffffffu, s, off);
        if (lane < KSEL) {
            out[(size_t)row * KSEL + lane] = e / s;
            if (writeIdx)
                out[(size_t)NXR * KSEL + (size_t)row * KSEL + lane] =
                    (float)sI[rl][lane];
        }
    }
}

// ---------------------------------------------------------------------------
extern "C" void kernel_launch(void* const* d_in, const int* in_sizes, int n_in,
                              void* d_out, int out_size) {
    const float* X = (const float*)d_in[0];  // feat_x [16384,128]
    const float* Y = (const float*)d_in[1];  // feat_y [16384,128]
    float* out = (float*)d_out;

    dim3 tb(32, 8);
    dim3 tg(NYC / 32, CDIM / 32);
    transpose_y_kernel<<<tg, tb>>>(Y);

    simtopk_kernel<<<NXR / 32, 256>>>(X, out, out_size);
}